// round 8
// baseline (speedup 1.0000x reference)
#include <cuda_runtime.h>
#include <cuda_fp16.h>
#include <cstdint>

#define N_NODES 100000
#define N_EDGES 1200000
#define FEATS   64
#define PAD     64                      // slots per node (max degree ~30)

typedef unsigned long long ull;

// scratch (load-time zero-initialized; g_cnt is re-zeroed by k_gather each run)
__device__ int g_cnt[N_NODES];
__device__ __align__(16) int    g_srcidx[(size_t)N_NODES * PAD];
__device__ __align__(16) __half g_xf[(size_t)N_NODES * FEATS];

// packed f32x2 FMA (Blackwell FFMA2)
__device__ __forceinline__ void fma2(ull& d, ull a, ull b) {
    asm("fma.rn.f32x2 %0, %1, %2, %0;" : "+l"(d) : "l"(a), "l"(b));
}
__device__ __forceinline__ float2 unpack2(ull v) {
    float2 r;
    asm("mov.b64 {%0, %1}, %2;" : "=f"(r.x), "=f"(r.y) : "l"(v));
    return r;
}

// ---------------------------------------------------------------------------
// K1: every block = scatter prologue (its slice of edges) + xform grid-stride.
// Scatter's atomic latency overlaps with xform's FMA work across warps/blocks.
// ---------------------------------------------------------------------------
#define XT_NODES  16
#define XF_BLOCKS 1184
#define XF_TILES  (N_NODES / XT_NODES)                    // 6250
#define EPB       ((N_EDGES + XF_BLOCKS - 1) / XF_BLOCKS) // 1014 edges/block

__global__ __launch_bounds__(256)
void k_build(const float* __restrict__ feat,
             const float* __restrict__ W,
             const int*   __restrict__ esrc,
             const int*   __restrict__ edst) {
    int tid = threadIdx.x;

    // ---- scatter prologue: up to 4 edges/thread, all atomics in flight ----
    {
        int ebase = blockIdx.x * EPB;
        int eend  = ebase + EPB;
        if (eend > N_EDGES) eend = N_EDGES;

        int d0 = -1, d1 = -1, d2 = -1, d3 = -1;
        int s0 = 0,  s1 = 0,  s2 = 0,  s3 = 0;
        int e0 = ebase + tid, e1 = e0 + 256, e2 = e1 + 256, e3 = e2 + 256;
        if (e0 < eend) { d0 = __ldg(&edst[e0]); s0 = __ldg(&esrc[e0]); }
        if (e1 < eend) { d1 = __ldg(&edst[e1]); s1 = __ldg(&esrc[e1]); }
        if (e2 < eend) { d2 = __ldg(&edst[e2]); s2 = __ldg(&esrc[e2]); }
        if (e3 < eend) { d3 = __ldg(&edst[e3]); s3 = __ldg(&esrc[e3]); }

        int p0 = (d0 >= 0) ? atomicAdd(&g_cnt[d0], 1) : PAD;
        int p1 = (d1 >= 0) ? atomicAdd(&g_cnt[d1], 1) : PAD;
        int p2 = (d2 >= 0) ? atomicAdd(&g_cnt[d2], 1) : PAD;
        int p3 = (d3 >= 0) ? atomicAdd(&g_cnt[d3], 1) : PAD;

        if (d0 >= 0 && p0 < PAD) g_srcidx[((size_t)d0 << 6) + p0] = s0;
        if (d1 >= 0 && p1 < PAD) g_srcidx[((size_t)d1 << 6) + p1] = s1;
        if (d2 >= 0 && p2 < PAD) g_srcidx[((size_t)d2 << 6) + p2] = s2;
        if (d3 >= 0 && p3 < PAD) g_srcidx[((size_t)d3 << 6) + p3] = s3;
    }

    // ---- xform: g_xf = fp16(feat @ W^T) ----
    __shared__ float Ws[FEATS * 66];        // row o at Ws[o*66 + d]
    __shared__ float fs[XT_NODES * 68];     // node n at fs[n*68 + d]

    #pragma unroll
    for (int i = tid; i < FEATS * FEATS; i += 256) {
        int o = i >> 6, d = i & 63;
        Ws[o * 66 + d] = W[i];
    }
    __syncthreads();

    int o  = tid & 63;
    int ns = tid >> 6;   // 0..3

    // low half of W row resident in registers (d = 0..31)
    ull wreg[16];
    #pragma unroll
    for (int k = 0; k < 16; k++)
        wreg[k] = *reinterpret_cast<const ull*>(&Ws[o * 66 + 2 * k]);
    const float* wHi = &Ws[o * 66 + 32];

    for (int t = blockIdx.x; t < XF_TILES; t += XF_BLOCKS) {
        int base = t * XT_NODES;
        __syncthreads();
        {
            int n  = tid >> 4;
            int dd = (tid & 15) * 4;
            float4 v = *reinterpret_cast<const float4*>(
                &feat[(size_t)(base + n) * FEATS + dd]);
            *reinterpret_cast<float4*>(&fs[n * 68 + dd]) = v;
        }
        __syncthreads();

        ull acc0 = 0, acc1 = 0, acc2 = 0, acc3 = 0;
        #pragma unroll
        for (int k = 0; k < 16; k++) {
            int d = 2 * k;
            ull a0 = *reinterpret_cast<const ull*>(&fs[(ns     ) * 68 + d]);
            ull a1 = *reinterpret_cast<const ull*>(&fs[(ns +  4) * 68 + d]);
            ull a2 = *reinterpret_cast<const ull*>(&fs[(ns +  8) * 68 + d]);
            ull a3 = *reinterpret_cast<const ull*>(&fs[(ns + 12) * 68 + d]);
            fma2(acc0, a0, wreg[k]);
            fma2(acc1, a1, wreg[k]);
            fma2(acc2, a2, wreg[k]);
            fma2(acc3, a3, wreg[k]);
        }
        #pragma unroll
        for (int k = 0; k < 16; k++) {
            int d = 32 + 2 * k;
            ull w  = *reinterpret_cast<const ull*>(&wHi[2 * k]);
            ull a0 = *reinterpret_cast<const ull*>(&fs[(ns     ) * 68 + d]);
            ull a1 = *reinterpret_cast<const ull*>(&fs[(ns +  4) * 68 + d]);
            ull a2 = *reinterpret_cast<const ull*>(&fs[(ns +  8) * 68 + d]);
            ull a3 = *reinterpret_cast<const ull*>(&fs[(ns + 12) * 68 + d]);
            fma2(acc0, a0, w);
            fma2(acc1, a1, w);
            fma2(acc2, a2, w);
            fma2(acc3, a3, w);
        }
        float2 r0 = unpack2(acc0), r1 = unpack2(acc1),
               r2 = unpack2(acc2), r3 = unpack2(acc3);
        g_xf[(size_t)(base + ns     ) * FEATS + o] = __float2half_rn(r0.x + r0.y);
        g_xf[(size_t)(base + ns +  4) * FEATS + o] = __float2half_rn(r1.x + r1.y);
        g_xf[(size_t)(base + ns +  8) * FEATS + o] = __float2half_rn(r2.x + r2.y);
        g_xf[(size_t)(base + ns + 12) * FEATS + o] = __float2half_rn(r3.x + r3.y);
    }
}

// ---------------------------------------------------------------------------
// K2: gather-mean + bias + relu. 8 threads/node.
// Pairwise fp16 add before fp32 convert; int4-vectorized index loads.
// Also resets g_cnt for the next graph replay (replaces the memset).
// ---------------------------------------------------------------------------
__device__ __forceinline__ void addPair(uint4 u0, uint4 u1,
    float& a0, float& a1, float& a2, float& a3,
    float& a4, float& a5, float& a6, float& a7) {
    __half2 h; float2 f;
    h = __hadd2(*reinterpret_cast<__half2*>(&u0.x), *reinterpret_cast<__half2*>(&u1.x));
    f = __half22float2(h); a0 += f.x; a1 += f.y;
    h = __hadd2(*reinterpret_cast<__half2*>(&u0.y), *reinterpret_cast<__half2*>(&u1.y));
    f = __half22float2(h); a2 += f.x; a3 += f.y;
    h = __hadd2(*reinterpret_cast<__half2*>(&u0.z), *reinterpret_cast<__half2*>(&u1.z));
    f = __half22float2(h); a4 += f.x; a5 += f.y;
    h = __hadd2(*reinterpret_cast<__half2*>(&u0.w), *reinterpret_cast<__half2*>(&u1.w));
    f = __half22float2(h); a6 += f.x; a7 += f.y;
}
__device__ __forceinline__ void addOne(uint4 u0,
    float& a0, float& a1, float& a2, float& a3,
    float& a4, float& a5, float& a6, float& a7) {
    float2 f;
    f = __half22float2(*reinterpret_cast<__half2*>(&u0.x)); a0 += f.x; a1 += f.y;
    f = __half22float2(*reinterpret_cast<__half2*>(&u0.y)); a2 += f.x; a3 += f.y;
    f = __half22float2(*reinterpret_cast<__half2*>(&u0.z)); a4 += f.x; a5 += f.y;
    f = __half22float2(*reinterpret_cast<__half2*>(&u0.w)); a6 += f.x; a7 += f.y;
}

__global__ __launch_bounds__(256)
void k_gather(const float* __restrict__ b,
              float* __restrict__ out) {
    int gid  = blockIdx.x * 256 + threadIdx.x;
    int node = gid >> 3;
    int l8   = gid & 7;

    int cnt = g_cnt[node];
    if (l8 == 0) g_cnt[node] = 0;          // reset for next replay (same-warp, after read)
    if (cnt > PAD) cnt = PAD;

    const int4* rowv = reinterpret_cast<const int4*>(&g_srcidx[(size_t)node << 6]);
    const size_t coff = (size_t)l8 * 8;

    float a0 = 0.f, a1 = 0.f, a2 = 0.f, a3 = 0.f,
          a4 = 0.f, a5 = 0.f, a6 = 0.f, a7 = 0.f;

    int nq  = cnt >> 2;
    int rem = cnt & 3;

    for (int q = 0; q < nq; q++) {
        int4 ix = rowv[q];
        uint4 u0 = *reinterpret_cast<const uint4*>(&g_xf[(size_t)ix.x * FEATS + coff]);
        uint4 u1 = *reinterpret_cast<const uint4*>(&g_xf[(size_t)ix.y * FEATS + coff]);
        uint4 u2 = *reinterpret_cast<const uint4*>(&g_xf[(size_t)ix.z * FEATS + coff]);
        uint4 u3 = *reinterpret_cast<const uint4*>(&g_xf[(size_t)ix.w * FEATS + coff]);
        addPair(u0, u1, a0, a1, a2, a3, a4, a5, a6, a7);
        addPair(u2, u3, a0, a1, a2, a3, a4, a5, a6, a7);
    }
    if (rem) {
        int4 ix = rowv[nq];                // padded row: over-read is safe, guarded below
        uint4 u0 = *reinterpret_cast<const uint4*>(&g_xf[(size_t)ix.x * FEATS + coff]);
        if (rem >= 2) {
            uint4 u1 = *reinterpret_cast<const uint4*>(&g_xf[(size_t)ix.y * FEATS + coff]);
            addPair(u0, u1, a0, a1, a2, a3, a4, a5, a6, a7);
            if (rem == 3) {
                uint4 u2 = *reinterpret_cast<const uint4*>(&g_xf[(size_t)ix.z * FEATS + coff]);
                addOne(u2, a0, a1, a2, a3, a4, a5, a6, a7);
            }
        } else {
            addOne(u0, a0, a1, a2, a3, a4, a5, a6, a7);
        }
    }

    float r = 1.0f / fmaxf((float)cnt, 1.0f);
    float4 b0 = *reinterpret_cast<const float4*>(&b[coff]);
    float4 b1 = *reinterpret_cast<const float4*>(&b[coff + 4]);

    float4 o0, o1;
    o0.x = fmaxf(fmaf(a0, r, b0.x), 0.f);
    o0.y = fmaxf(fmaf(a1, r, b0.y), 0.f);
    o0.z = fmaxf(fmaf(a2, r, b0.z), 0.f);
    o0.w = fmaxf(fmaf(a3, r, b0.w), 0.f);
    o1.x = fmaxf(fmaf(a4, r, b1.x), 0.f);
    o1.y = fmaxf(fmaf(a5, r, b1.y), 0.f);
    o1.z = fmaxf(fmaf(a6, r, b1.z), 0.f);
    o1.w = fmaxf(fmaf(a7, r, b1.w), 0.f);

    float* op = &out[(size_t)node * FEATS + coff];
    *reinterpret_cast<float4*>(op)     = o0;
    *reinterpret_cast<float4*>(op + 4) = o1;
}

// ---------------------------------------------------------------------------
extern "C" void kernel_launch(void* const* d_in, const int* in_sizes, int n_in,
                              void* d_out, int out_size) {
    const float* feat = (const float*)d_in[0];
    const int*   esrc = (const int*)  d_in[1];
    const int*   edst = (const int*)  d_in[2];
    const float* W    = (const float*)d_in[3];
    const float* b    = (const float*)d_in[4];
    float* out = (float*)d_out;

    k_build<<<XF_BLOCKS, 256>>>(feat, W, esrc, edst);
    k_gather<<<(N_NODES * 8) / 256, 256>>>(b, out);
}

// round 9
// speedup vs baseline: 1.1570x; 1.1570x over previous
#include <cuda_runtime.h>
#include <cuda_fp16.h>
#include <cstdint>

#define N_NODES 100000
#define N_EDGES 1200000
#define FEATS   64
#define PAD     64                      // slots per node (max degree ~30)

typedef unsigned long long ull;

// scratch
__device__ int g_cnt[N_NODES];
__device__ __align__(16) int    g_srcidx[(size_t)N_NODES * PAD];
__device__ __align__(16) __half g_xf[(size_t)N_NODES * FEATS];

// packed f32x2 FMA (Blackwell FFMA2)
__device__ __forceinline__ void fma2(ull& d, ull a, ull b) {
    asm("fma.rn.f32x2 %0, %1, %2, %0;" : "+l"(d) : "l"(a), "l"(b));
}
__device__ __forceinline__ float2 unpack2(ull v) {
    float2 r;
    asm("mov.b64 {%0, %1}, %2;" : "=f"(r.x), "=f"(r.y) : "l"(v));
    return r;
}

// ---------------------------------------------------------------------------
// K1: every block = scatter prologue (its slice of edges) + xform grid-stride.
// W fully register-resident; activations via LDS.128 (2 fma2 per load).
// ---------------------------------------------------------------------------
#define XT_NODES  16
#define XF_BLOCKS 1184
#define XF_TILES  (N_NODES / XT_NODES)                    // 6250
#define EPB       ((N_EDGES + XF_BLOCKS - 1) / XF_BLOCKS) // 1014 edges/block

__global__ __launch_bounds__(256)
void k_build(const float* __restrict__ feat,
             const float* __restrict__ W,
             const int*   __restrict__ esrc,
             const int*   __restrict__ edst) {
    int tid = threadIdx.x;

    // ---- scatter prologue: up to 4 edges/thread, all atomics in flight ----
    {
        int ebase = blockIdx.x * EPB;
        int eend  = ebase + EPB;
        if (eend > N_EDGES) eend = N_EDGES;

        int d0 = -1, d1 = -1, d2 = -1, d3 = -1;
        int s0 = 0,  s1 = 0,  s2 = 0,  s3 = 0;
        int e0 = ebase + tid, e1 = e0 + 256, e2 = e1 + 256, e3 = e2 + 256;
        if (e0 < eend) { d0 = __ldg(&edst[e0]); s0 = __ldg(&esrc[e0]); }
        if (e1 < eend) { d1 = __ldg(&edst[e1]); s1 = __ldg(&esrc[e1]); }
        if (e2 < eend) { d2 = __ldg(&edst[e2]); s2 = __ldg(&esrc[e2]); }
        if (e3 < eend) { d3 = __ldg(&edst[e3]); s3 = __ldg(&esrc[e3]); }

        int p0 = (d0 >= 0) ? atomicAdd(&g_cnt[d0], 1) : PAD;
        int p1 = (d1 >= 0) ? atomicAdd(&g_cnt[d1], 1) : PAD;
        int p2 = (d2 >= 0) ? atomicAdd(&g_cnt[d2], 1) : PAD;
        int p3 = (d3 >= 0) ? atomicAdd(&g_cnt[d3], 1) : PAD;

        if (d0 >= 0 && p0 < PAD) g_srcidx[((size_t)d0 << 6) + p0] = s0;
        if (d1 >= 0 && p1 < PAD) g_srcidx[((size_t)d1 << 6) + p1] = s1;
        if (d2 >= 0 && p2 < PAD) g_srcidx[((size_t)d2 << 6) + p2] = s2;
        if (d3 >= 0 && p3 < PAD) g_srcidx[((size_t)d3 << 6) + p3] = s3;
    }

    // ---- xform: g_xf = fp16(feat @ W^T) ----
    __shared__ float Ws[FEATS * 66];        // staging only: row o at Ws[o*66+d]
    __shared__ float fs[XT_NODES * 68];     // node n at fs[n*68 + d] (68 = 17 float4)

    #pragma unroll
    for (int i = tid; i < FEATS * FEATS; i += 256) {
        int o = i >> 6, d = i & 63;
        Ws[o * 66 + d] = W[i];
    }
    __syncthreads();

    int o  = tid & 63;
    int ns = tid >> 6;   // 0..3

    // full W row for this output column in registers (32 packed pairs)
    ull wreg[32];
    #pragma unroll
    for (int k = 0; k < 32; k++)
        wreg[k] = *reinterpret_cast<const ull*>(&Ws[o * 66 + 2 * k]);

    const float4* fs4 = reinterpret_cast<const float4*>(fs);  // row n = n*17

    for (int t = blockIdx.x; t < XF_TILES; t += XF_BLOCKS) {
        int base = t * XT_NODES;
        __syncthreads();
        {
            int n  = tid >> 4;
            int dd = (tid & 15) * 4;
            float4 v = *reinterpret_cast<const float4*>(
                &feat[(size_t)(base + n) * FEATS + dd]);
            *reinterpret_cast<float4*>(&fs[n * 68 + dd]) = v;
        }
        __syncthreads();

        ull acc0 = 0, acc1 = 0, acc2 = 0, acc3 = 0;
        #pragma unroll
        for (int k = 0; k < 16; k++) {               // d = 4k .. 4k+3
            float4 a0 = fs4[(ns     ) * 17 + k];
            float4 a1 = fs4[(ns +  4) * 17 + k];
            float4 a2 = fs4[(ns +  8) * 17 + k];
            float4 a3 = fs4[(ns + 12) * 17 + k];
            ull w0 = wreg[2 * k], w1 = wreg[2 * k + 1];
            fma2(acc0, *reinterpret_cast<ull*>(&a0)    , w0);
            fma2(acc0, *(reinterpret_cast<ull*>(&a0)+1), w1);
            fma2(acc1, *reinterpret_cast<ull*>(&a1)    , w0);
            fma2(acc1, *(reinterpret_cast<ull*>(&a1)+1), w1);
            fma2(acc2, *reinterpret_cast<ull*>(&a2)    , w0);
            fma2(acc2, *(reinterpret_cast<ull*>(&a2)+1), w1);
            fma2(acc3, *reinterpret_cast<ull*>(&a3)    , w0);
            fma2(acc3, *(reinterpret_cast<ull*>(&a3)+1), w1);
        }
        float2 r0 = unpack2(acc0), r1 = unpack2(acc1),
               r2 = unpack2(acc2), r3 = unpack2(acc3);
        g_xf[(size_t)(base + ns     ) * FEATS + o] = __float2half_rn(r0.x + r0.y);
        g_xf[(size_t)(base + ns +  4) * FEATS + o] = __float2half_rn(r1.x + r1.y);
        g_xf[(size_t)(base + ns +  8) * FEATS + o] = __float2half_rn(r2.x + r2.y);
        g_xf[(size_t)(base + ns + 12) * FEATS + o] = __float2half_rn(r3.x + r3.y);
    }
}

// ---------------------------------------------------------------------------
// K2: gather-mean + bias + relu (R5-proven variant: scalar index loads,
// 2-edge unroll, fp32 accumulate; 28 regs, high occupancy).
// ---------------------------------------------------------------------------
__global__ __launch_bounds__(256)
void k_gather(const float* __restrict__ b,
              float* __restrict__ out) {
    int gid  = blockIdx.x * 256 + threadIdx.x;
    int node = gid >> 3;
    int l8   = gid & 7;

    int cnt = g_cnt[node];
    if (cnt > PAD) cnt = PAD;
    const int* row = &g_srcidx[(size_t)node << 6];

    float a0 = 0.f, a1 = 0.f, a2 = 0.f, a3 = 0.f,
          a4 = 0.f, a5 = 0.f, a6 = 0.f, a7 = 0.f;

    const size_t coff = (size_t)l8 * 8;

    int i = 0;
    for (; i + 2 <= cnt; i += 2) {
        int n0 = row[i];
        int n1 = row[i + 1];
        uint4 u0 = *reinterpret_cast<const uint4*>(&g_xf[(size_t)n0 * FEATS + coff]);
        uint4 u1 = *reinterpret_cast<const uint4*>(&g_xf[(size_t)n1 * FEATS + coff]);
        float2 f;
        f = __half22float2(*reinterpret_cast<__half2*>(&u0.x)); a0 += f.x; a1 += f.y;
        f = __half22float2(*reinterpret_cast<__half2*>(&u0.y)); a2 += f.x; a3 += f.y;
        f = __half22float2(*reinterpret_cast<__half2*>(&u0.z)); a4 += f.x; a5 += f.y;
        f = __half22float2(*reinterpret_cast<__half2*>(&u0.w)); a6 += f.x; a7 += f.y;
        f = __half22float2(*reinterpret_cast<__half2*>(&u1.x)); a0 += f.x; a1 += f.y;
        f = __half22float2(*reinterpret_cast<__half2*>(&u1.y)); a2 += f.x; a3 += f.y;
        f = __half22float2(*reinterpret_cast<__half2*>(&u1.z)); a4 += f.x; a5 += f.y;
        f = __half22float2(*reinterpret_cast<__half2*>(&u1.w)); a6 += f.x; a7 += f.y;
    }
    if (i < cnt) {
        int n0 = row[i];
        uint4 u0 = *reinterpret_cast<const uint4*>(&g_xf[(size_t)n0 * FEATS + coff]);
        float2 f;
        f = __half22float2(*reinterpret_cast<__half2*>(&u0.x)); a0 += f.x; a1 += f.y;
        f = __half22float2(*reinterpret_cast<__half2*>(&u0.y)); a2 += f.x; a3 += f.y;
        f = __half22float2(*reinterpret_cast<__half2*>(&u0.z)); a4 += f.x; a5 += f.y;
        f = __half22float2(*reinterpret_cast<__half2*>(&u0.w)); a6 += f.x; a7 += f.y;
    }

    float r = 1.0f / fmaxf((float)cnt, 1.0f);
    float4 b0 = *reinterpret_cast<const float4*>(&b[coff]);
    float4 b1 = *reinterpret_cast<const float4*>(&b[coff + 4]);

    float4 o0, o1;
    o0.x = fmaxf(fmaf(a0, r, b0.x), 0.f);
    o0.y = fmaxf(fmaf(a1, r, b0.y), 0.f);
    o0.z = fmaxf(fmaf(a2, r, b0.z), 0.f);
    o0.w = fmaxf(fmaf(a3, r, b0.w), 0.f);
    o1.x = fmaxf(fmaf(a4, r, b1.x), 0.f);
    o1.y = fmaxf(fmaf(a5, r, b1.y), 0.f);
    o1.z = fmaxf(fmaf(a6, r, b1.z), 0.f);
    o1.w = fmaxf(fmaf(a7, r, b1.w), 0.f);

    float* op = &out[(size_t)node * FEATS + coff];
    *reinterpret_cast<float4*>(op)     = o0;
    *reinterpret_cast<float4*>(op + 4) = o1;
}

// ---------------------------------------------------------------------------
extern "C" void kernel_launch(void* const* d_in, const int* in_sizes, int n_in,
                              void* d_out, int out_size) {
    const float* feat = (const float*)d_in[0];
    const int*   esrc = (const int*)  d_in[1];
    const int*   edst = (const int*)  d_in[2];
    const float* W    = (const float*)d_in[3];
    const float* b    = (const float*)d_in[4];
    float* out = (float*)d_out;

    void* p_cnt = nullptr;
    cudaGetSymbolAddress(&p_cnt, g_cnt);
    cudaMemsetAsync(p_cnt, 0, sizeof(int) * N_NODES);

    k_build<<<XF_BLOCKS, 256>>>(feat, W, esrc, edst);
    k_gather<<<(N_NODES * 8) / 256, 256>>>(b, out);
}

// round 10
// speedup vs baseline: 1.2022x; 1.0391x over previous
#include <cuda_runtime.h>
#include <cuda_fp16.h>
#include <cstdint>

#define N_NODES 100000
#define N_EDGES 1200000
#define FEATS   64
#define PAD     64                      // slots per node (max degree ~30)

typedef unsigned long long ull;

// scratch
__device__ int g_cnt[N_NODES];
__device__ __align__(16) int    g_srcidx[(size_t)N_NODES * PAD];
__device__ __align__(16) __half g_xf[(size_t)N_NODES * FEATS];

// packed f32x2 FMA (Blackwell FFMA2)
__device__ __forceinline__ void fma2(ull& d, ull a, ull b) {
    asm("fma.rn.f32x2 %0, %1, %2, %0;" : "+l"(d) : "l"(a), "l"(b));
}
__device__ __forceinline__ float2 unpack2(ull v) {
    float2 r;
    asm("mov.b64 {%0, %1}, %2;" : "=f"(r.x), "=f"(r.y) : "l"(v));
    return r;
}
#define XBAR() asm volatile("bar.sync 1, 256;" ::: "memory")   // xform warps only

// ---------------------------------------------------------------------------
// K1: warp-specialized build.
// threads 0..255  : xform  g_xf = fp16(feat @ W^T)   (grid-stride tiles)
// threads 256..287: scatter this block's 1014-edge slice into padded CSR
// Scatter atomics overlap xform FMAs on the same SM at all times.
// ---------------------------------------------------------------------------
#define XT_NODES  16
#define XF_BLOCKS 1184
#define XF_TILES  (N_NODES / XT_NODES)                    // 6250
#define EPB       ((N_EDGES + XF_BLOCKS - 1) / XF_BLOCKS) // 1014 edges/block

__global__ __launch_bounds__(288)
void k_build(const float* __restrict__ feat,
             const float* __restrict__ W,
             const int*   __restrict__ esrc,
             const int*   __restrict__ edst) {
    int tid = threadIdx.x;

    if (tid >= 256) {
        // ---- scatter warp: 32 threads, ~32 edges each, 4-deep atomic MLP ----
        int lane  = tid - 256;
        int ebase = blockIdx.x * EPB;
        int eend  = ebase + EPB;
        if (eend > N_EDGES) eend = N_EDGES;

        for (int j = ebase + lane; j < eend; j += 128) {
            int e0 = j, e1 = j + 32, e2 = j + 64, e3 = j + 96;
            int d0 = -1, d1 = -1, d2 = -1, d3 = -1;
            int s0 = 0,  s1 = 0,  s2 = 0,  s3 = 0;
            d0 = __ldg(&edst[e0]); s0 = __ldg(&esrc[e0]);
            if (e1 < eend) { d1 = __ldg(&edst[e1]); s1 = __ldg(&esrc[e1]); }
            if (e2 < eend) { d2 = __ldg(&edst[e2]); s2 = __ldg(&esrc[e2]); }
            if (e3 < eend) { d3 = __ldg(&edst[e3]); s3 = __ldg(&esrc[e3]); }

            int p0 = atomicAdd(&g_cnt[d0], 1);
            int p1 = (d1 >= 0) ? atomicAdd(&g_cnt[d1], 1) : PAD;
            int p2 = (d2 >= 0) ? atomicAdd(&g_cnt[d2], 1) : PAD;
            int p3 = (d3 >= 0) ? atomicAdd(&g_cnt[d3], 1) : PAD;

            if (p0 < PAD)            g_srcidx[((size_t)d0 << 6) + p0] = s0;
            if (d1 >= 0 && p1 < PAD) g_srcidx[((size_t)d1 << 6) + p1] = s1;
            if (d2 >= 0 && p2 < PAD) g_srcidx[((size_t)d2 << 6) + p2] = s2;
            if (d3 >= 0 && p3 < PAD) g_srcidx[((size_t)d3 << 6) + p3] = s3;
        }
        return;   // scatter warp exits; xform warps sync on named barrier 1
    }

    // ---- xform warps (256 threads) ----
    __shared__ float Ws[FEATS * 66];        // row o at Ws[o*66 + d]
    __shared__ float fs[XT_NODES * 68];     // node n at fs[n*68 + d] (17 float4)

    #pragma unroll
    for (int i = tid; i < FEATS * FEATS; i += 256) {
        int o = i >> 6, d = i & 63;
        Ws[o * 66 + d] = W[i];
    }
    XBAR();

    int o  = tid & 63;
    int ns = tid >> 6;   // 0..3

    // low half of W row in registers (d = 0..31); high half via shared broadcast
    ull wreg[16];
    #pragma unroll
    for (int k = 0; k < 16; k++)
        wreg[k] = *reinterpret_cast<const ull*>(&Ws[o * 66 + 2 * k]);
    const float* wHi = &Ws[o * 66 + 32];

    const float4* fs4 = reinterpret_cast<const float4*>(fs);  // row n = n*17

    for (int t = blockIdx.x; t < XF_TILES; t += XF_BLOCKS) {
        int base = t * XT_NODES;
        XBAR();
        {
            int n  = tid >> 4;
            int dd = (tid & 15) * 4;
            float4 v = *reinterpret_cast<const float4*>(
                &feat[(size_t)(base + n) * FEATS + dd]);
            *reinterpret_cast<float4*>(&fs[n * 68 + dd]) = v;
        }
        XBAR();

        ull acc0 = 0, acc1 = 0, acc2 = 0, acc3 = 0;
        #pragma unroll
        for (int k = 0; k < 8; k++) {               // d = 4k..4k+3 (regs)
            float4 a0 = fs4[(ns     ) * 17 + k];
            float4 a1 = fs4[(ns +  4) * 17 + k];
            float4 a2 = fs4[(ns +  8) * 17 + k];
            float4 a3 = fs4[(ns + 12) * 17 + k];
            ull w0 = wreg[2 * k], w1 = wreg[2 * k + 1];
            fma2(acc0, *reinterpret_cast<ull*>(&a0)    , w0);
            fma2(acc0, *(reinterpret_cast<ull*>(&a0)+1), w1);
            fma2(acc1, *reinterpret_cast<ull*>(&a1)    , w0);
            fma2(acc1, *(reinterpret_cast<ull*>(&a1)+1), w1);
            fma2(acc2, *reinterpret_cast<ull*>(&a2)    , w0);
            fma2(acc2, *(reinterpret_cast<ull*>(&a2)+1), w1);
            fma2(acc3, *reinterpret_cast<ull*>(&a3)    , w0);
            fma2(acc3, *(reinterpret_cast<ull*>(&a3)+1), w1);
        }
        #pragma unroll
        for (int k = 8; k < 16; k++) {              // d = 32..63 (shared bcast)
            float4 a0 = fs4[(ns     ) * 17 + k];
            float4 a1 = fs4[(ns +  4) * 17 + k];
            float4 a2 = fs4[(ns +  8) * 17 + k];
            float4 a3 = fs4[(ns + 12) * 17 + k];
            ull w0 = *reinterpret_cast<const ull*>(&wHi[4 * (k - 8)]);
            ull w1 = *reinterpret_cast<const ull*>(&wHi[4 * (k - 8) + 2]);
            fma2(acc0, *reinterpret_cast<ull*>(&a0)    , w0);
            fma2(acc0, *(reinterpret_cast<ull*>(&a0)+1), w1);
            fma2(acc1, *reinterpret_cast<ull*>(&a1)    , w0);
            fma2(acc1, *(reinterpret_cast<ull*>(&a1)+1), w1);
            fma2(acc2, *reinterpret_cast<ull*>(&a2)    , w0);
            fma2(acc2, *(reinterpret_cast<ull*>(&a2)+1), w1);
            fma2(acc3, *reinterpret_cast<ull*>(&a3)    , w0);
            fma2(acc3, *(reinterpret_cast<ull*>(&a3)+1), w1);
        }
        float2 r0 = unpack2(acc0), r1 = unpack2(acc1),
               r2 = unpack2(acc2), r3 = unpack2(acc3);
        g_xf[(size_t)(base + ns     ) * FEATS + o] = __float2half_rn(r0.x + r0.y);
        g_xf[(size_t)(base + ns +  4) * FEATS + o] = __float2half_rn(r1.x + r1.y);
        g_xf[(size_t)(base + ns +  8) * FEATS + o] = __float2half_rn(r2.x + r2.y);
        g_xf[(size_t)(base + ns + 12) * FEATS + o] = __float2half_rn(r3.x + r3.y);
    }
}

// ---------------------------------------------------------------------------
// K2: gather-mean + bias + relu. Same structure as R9 (proven 24us); single
// change: pairwise HADD2 of the two unrolled edges before fp32 convert.
// ---------------------------------------------------------------------------
__global__ __launch_bounds__(256)
void k_gather(const float* __restrict__ b,
              float* __restrict__ out) {
    int gid  = blockIdx.x * 256 + threadIdx.x;
    int node = gid >> 3;
    int l8   = gid & 7;

    int cnt = g_cnt[node];
    if (cnt > PAD) cnt = PAD;
    const int* row = &g_srcidx[(size_t)node << 6];

    float a0 = 0.f, a1 = 0.f, a2 = 0.f, a3 = 0.f,
          a4 = 0.f, a5 = 0.f, a6 = 0.f, a7 = 0.f;

    const size_t coff = (size_t)l8 * 8;

    int i = 0;
    for (; i + 2 <= cnt; i += 2) {
        int n0 = row[i];
        int n1 = row[i + 1];
        uint4 u0 = *reinterpret_cast<const uint4*>(&g_xf[(size_t)n0 * FEATS + coff]);
        uint4 u1 = *reinterpret_cast<const uint4*>(&g_xf[(size_t)n1 * FEATS + coff]);
        __half2 h; float2 f;
        h = __hadd2(*reinterpret_cast<__half2*>(&u0.x), *reinterpret_cast<__half2*>(&u1.x));
        f = __half22float2(h); a0 += f.x; a1 += f.y;
        h = __hadd2(*reinterpret_cast<__half2*>(&u0.y), *reinterpret_cast<__half2*>(&u1.y));
        f = __half22float2(h); a2 += f.x; a3 += f.y;
        h = __hadd2(*reinterpret_cast<__half2*>(&u0.z), *reinterpret_cast<__half2*>(&u1.z));
        f = __half22float2(h); a4 += f.x; a5 += f.y;
        h = __hadd2(*reinterpret_cast<__half2*>(&u0.w), *reinterpret_cast<__half2*>(&u1.w));
        f = __half22float2(h); a6 += f.x; a7 += f.y;
    }
    if (i < cnt) {
        int n0 = row[i];
        uint4 u0 = *reinterpret_cast<const uint4*>(&g_xf[(size_t)n0 * FEATS + coff]);
        float2 f;
        f = __half22float2(*reinterpret_cast<__half2*>(&u0.x)); a0 += f.x; a1 += f.y;
        f = __half22float2(*reinterpret_cast<__half2*>(&u0.y)); a2 += f.x; a3 += f.y;
        f = __half22float2(*reinterpret_cast<__half2*>(&u0.z)); a4 += f.x; a5 += f.y;
        f = __half22float2(*reinterpret_cast<__half2*>(&u0.w)); a6 += f.x; a7 += f.y;
    }

    float r = 1.0f / fmaxf((float)cnt, 1.0f);
    float4 b0 = *reinterpret_cast<const float4*>(&b[coff]);
    float4 b1 = *reinterpret_cast<const float4*>(&b[coff + 4]);

    float4 o0, o1;
    o0.x = fmaxf(fmaf(a0, r, b0.x), 0.f);
    o0.y = fmaxf(fmaf(a1, r, b0.y), 0.f);
    o0.z = fmaxf(fmaf(a2, r, b0.z), 0.f);
    o0.w = fmaxf(fmaf(a3, r, b0.w), 0.f);
    o1.x = fmaxf(fmaf(a4, r, b1.x), 0.f);
    o1.y = fmaxf(fmaf(a5, r, b1.y), 0.f);
    o1.z = fmaxf(fmaf(a6, r, b1.z), 0.f);
    o1.w = fmaxf(fmaf(a7, r, b1.w), 0.f);

    float* op = &out[(size_t)node * FEATS + coff];
    *reinterpret_cast<float4*>(op)     = o0;
    *reinterpret_cast<float4*>(op + 4) = o1;
}

// ---------------------------------------------------------------------------
extern "C" void kernel_launch(void* const* d_in, const int* in_sizes, int n_in,
                              void* d_out, int out_size) {
    const float* feat = (const float*)d_in[0];
    const int*   esrc = (const int*)  d_in[1];
    const int*   edst = (const int*)  d_in[2];
    const float* W    = (const float*)d_in[3];
    const float* b    = (const float*)d_in[4];
    float* out = (float*)d_out;

    void* p_cnt = nullptr;
    cudaGetSymbolAddress(&p_cnt, g_cnt);
    cudaMemsetAsync(p_cnt, 0, sizeof(int) * N_NODES);

    k_build<<<XF_BLOCKS, 288>>>(feat, W, esrc, edst);
    k_gather<<<(N_NODES * 8) / 256, 256>>>(b, out);
}